// round 1
// baseline (speedup 1.0000x reference)
#include <cuda_runtime.h>
#include <math.h>

// Problem constants
#define BATCH 32768
#define DIM   1024
#define HID   256

// GEMM tiling
#define BM 128
#define BN 128
#define BK 16
#define TM 8
#define TN 8
#define NT 256

// Scratch (device globals — no runtime allocation)
__device__ float g_H[(size_t)BATCH * HID];      // 32 MB: relu(F @ Wg1 + b)
__device__ float g_comp[(size_t)BATCH * DIM];   // 128 MB: competitive-sparse output

__device__ __forceinline__ float sigmoidf_(float x) {
    return 1.0f / (1.0f + expf(-x));
}

// ---------------------------------------------------------------------------
// GEMM kernels.
// EPI==0:  g_H = relu(F[B,1024] @ Wg1[1024,256] + bg1)          (K=1024, N=256)
// EPI==1:  g_comp = epi(g_H[B,256] @ Wg2[256,1024] + bg2)       (K=256,  N=1024)
//          epi: gw = sigmoid(x); g = F*gw; comp = (g > 0.3) ? 0 : g
// NOTE: the reference's "competition" branch is dead code: win == False always
// (other_max = max(f, .) >= f, so other_max < f never holds). comp reduces to
// the threshold pass-through above — exact identity, skips the 1024x1024 GEMM.
// ---------------------------------------------------------------------------
template <int EPI>
__global__ __launch_bounds__(NT) void gemm_k(
    const float* __restrict__ F,
    const float* __restrict__ W,
    const float* __restrict__ bias)
{
    constexpr int K = (EPI == 0) ? DIM : HID;
    constexpr int N = (EPI == 0) ? HID : DIM;

    __shared__ float As[BK][BM];
    __shared__ float Ws[BK][BN];

    const int tid = threadIdx.x;
    const int tx  = tid & 15;      // 0..15 col group
    const int ty  = tid >> 4;      // 0..15 row group
    const int bx  = blockIdx.x;
    const int by  = blockIdx.y;

    const float* A = (EPI == 0) ? F : g_H;
    float*       C = (EPI == 0) ? g_H : g_comp;

    const float* Ab = A + (size_t)by * BM * K;
    const float* Wb = W + (size_t)bx * BN;

    float acc[TM][TN];
#pragma unroll
    for (int i = 0; i < TM; i++)
#pragma unroll
        for (int j = 0; j < TN; j++) acc[i][j] = 0.0f;

    for (int kt = 0; kt < K; kt += BK) {
        // Load A tile (BM x BK), store transposed into As[k][m].
        // 128 rows x 4 float4 = 512 loads, 2 per thread.
#pragma unroll
        for (int u = 0; u < 2; u++) {
            int l  = tid + u * NT;
            int r  = l >> 2;
            int c4 = l & 3;
            float4 v = *(const float4*)(Ab + (size_t)r * K + kt + c4 * 4);
            As[c4 * 4 + 0][r] = v.x;
            As[c4 * 4 + 1][r] = v.y;
            As[c4 * 4 + 2][r] = v.z;
            As[c4 * 4 + 3][r] = v.w;
        }
        // Load W tile (BK x BN). 16 rows x 32 float4 = 512 loads, 2 per thread.
#pragma unroll
        for (int u = 0; u < 2; u++) {
            int l  = tid + u * NT;
            int r  = l >> 5;
            int c4 = l & 31;
            *(float4*)(&Ws[r][c4 * 4]) =
                *(const float4*)(Wb + (size_t)(kt + r) * N + c4 * 4);
        }
        __syncthreads();

#pragma unroll
        for (int k = 0; k < BK; k++) {
            float a[TM], b[TN];
#pragma unroll
            for (int i = 0; i < TM; i++) a[i] = As[k][ty * TM + i];
#pragma unroll
            for (int j = 0; j < TN; j++) b[j] = Ws[k][tx * TN + j];
#pragma unroll
            for (int i = 0; i < TM; i++)
#pragma unroll
                for (int j = 0; j < TN; j++)
                    acc[i][j] = fmaf(a[i], b[j], acc[i][j]);
        }
        __syncthreads();
    }

    // Epilogue
#pragma unroll
    for (int i = 0; i < TM; i++) {
        int r = by * BM + ty * TM + i;
#pragma unroll
        for (int j = 0; j < TN; j++) {
            int c = bx * BN + tx * TN + j;
            float x = acc[i][j] + bias[c];
            float o;
            if (EPI == 0) {
                o = fmaxf(x, 0.0f);
            } else {
                float gw = sigmoidf_(x);
                float g  = F[(size_t)r * DIM + c] * gw;
                o = (g > 0.3f) ? 0.0f : g;   // win == False always
            }
            C[(size_t)r * N + c] = o;
        }
    }
}

// ---------------------------------------------------------------------------
// Row-wise post-processing: 256 threads, R3 rows per CTA.
// Each thread owns columns {t, t+256, t+512, t+768}; w_r2 columns live in
// registers, amortized across R3 rows (avoids 2GB of L2 traffic).
// ---------------------------------------------------------------------------
#define R3 32

__global__ __launch_bounds__(256) void rowpost_k(
    const float* __restrict__ w_r1, const float* __restrict__ b_r1,
    const float* __restrict__ w_r2, const float* __restrict__ b_r2,
    const float* __restrict__ w_m1, const float* __restrict__ b_m1,
    const float* __restrict__ w_m2, const float* __restrict__ b_m2,
    float* __restrict__ out)
{
    const int tid  = threadIdx.x;
    const int lane = tid & 31;
    const int wid  = tid >> 5;

    __shared__ float sA[8], sB[8], sC[8], sD[8];

    // Per-thread slice of w_r2 / b_r2 (columns tid + 256*j), reused all rows.
    float wr2[16][4];
#pragma unroll
    for (int k = 0; k < 16; k++)
#pragma unroll
        for (int j = 0; j < 4; j++)
            wr2[k][j] = w_r2[k * DIM + tid + 256 * j];
    float br2r[4];
#pragma unroll
    for (int j = 0; j < 4; j++) br2r[j] = b_r2[tid + 256 * j];

    for (int rr = 0; rr < R3; rr++) {
        size_t row = (size_t)blockIdx.x * R3 + rr;
        const float* cr = g_comp + row * DIM;

        __syncthreads();  // protect smem reuse across rows

        float v[4];
#pragma unroll
        for (int j = 0; j < 4; j++) v[j] = cr[tid + 256 * j];

        // cur_sp = mean(|comp| < 0.1)
        float cnt = 0.0f;
#pragma unroll
        for (int j = 0; j < 4; j++) cnt += (fabsf(v[j]) < 0.1f) ? 1.0f : 0.0f;
#pragma unroll
        for (int o = 16; o; o >>= 1) cnt += __shfl_xor_sync(0xffffffffu, cnt, o);
        if (lane == 0) sD[wid] = cnt;
        __syncthreads();
        cnt = 0.0f;
#pragma unroll
        for (int w = 0; w < 8; w++) cnt += sD[w];
        float cur_sp = cnt * (1.0f / 1024.0f);

        // hr = relu([cur_sp, 0.1] @ w_r1 + b_r1)   (computed redundantly per thread)
        float hr[16];
#pragma unroll
        for (int k = 0; k < 16; k++) {
            float x = fmaf(cur_sp, w_r1[k], fmaf(0.1f, w_r1[16 + k], b_r1[k]));
            hr[k] = fmaxf(x, 0.0f);
        }

        // rw = sigmoid(hr @ w_r2 + b_r2); dyn = comp * rw; row stats
        float dyn[4];
        float s1 = 0.0f, s2 = 0.0f, mx = -INFINITY;
#pragma unroll
        for (int j = 0; j < 4; j++) {
            float a = br2r[j];
#pragma unroll
            for (int k = 0; k < 16; k++) a = fmaf(hr[k], wr2[k][j], a);
            float rw = sigmoidf_(a);
            float d  = v[j] * rw;
            dyn[j] = d;
            s1 += d;
            s2 = fmaf(d, d, s2);
            mx = fmaxf(mx, d);
        }
#pragma unroll
        for (int o = 16; o; o >>= 1) {
            s1 += __shfl_xor_sync(0xffffffffu, s1, o);
            s2 += __shfl_xor_sync(0xffffffffu, s2, o);
            mx = fmaxf(mx, __shfl_xor_sync(0xffffffffu, mx, o));
        }
        if (lane == 0) { sA[wid] = s1; sB[wid] = s2; sC[wid] = mx; }
        __syncthreads();
        s1 = 0.0f; s2 = 0.0f; mx = -INFINITY;
#pragma unroll
        for (int w = 0; w < 8; w++) {
            s1 += sA[w];
            s2 += sB[w];
            mx = fmaxf(mx, sC[w]);
        }

        float fmean = s1 * (1.0f / 1024.0f);
        float var   = (s2 - s1 * fmean) * (1.0f / 1023.0f);  // ddof=1
        var = fmaxf(var, 0.0f);
        float fstd = sqrtf(var);

        // thr = sigmoid(relu([fmean, fstd, fmax] @ w_m1 + b_m1) @ w_m2 + b_m2)
        float a2 = b_m2[0];
#pragma unroll
        for (int k = 0; k < 16; k++) {
            float x = fmaf(fmean, w_m1[k],
                      fmaf(fstd, w_m1[16 + k],
                      fmaf(mx,   w_m1[32 + k], b_m1[k])));
            a2 = fmaf(fmaxf(x, 0.0f), w_m2[k], a2);
        }
        float thr = sigmoidf_(a2);

        float* orow = out + row * DIM;
#pragma unroll
        for (int j = 0; j < 4; j++)
            orow[tid + 256 * j] = (fabsf(dyn[j]) > thr) ? dyn[j] : 0.0f;
    }
}

// ---------------------------------------------------------------------------
// Launch
// ---------------------------------------------------------------------------
extern "C" void kernel_launch(void* const* d_in, const int* in_sizes, int n_in,
                              void* d_out, int out_size)
{
    const float* F   = (const float*)d_in[0];
    const float* wg1 = (const float*)d_in[1];
    const float* bg1 = (const float*)d_in[2];
    const float* wg2 = (const float*)d_in[3];
    const float* bg2 = (const float*)d_in[4];
    // d_in[5..8] = w_c1, b_c1, w_c2, b_c2 — dead code (win == False always)
    const float* wr1 = (const float*)d_in[9];
    const float* br1 = (const float*)d_in[10];
    const float* wr2 = (const float*)d_in[11];
    const float* br2 = (const float*)d_in[12];
    const float* wm1 = (const float*)d_in[13];
    const float* bm1 = (const float*)d_in[14];
    const float* wm2 = (const float*)d_in[15];
    const float* bm2 = (const float*)d_in[16];
    float* out = (float*)d_out;

    (void)in_sizes; (void)n_in; (void)out_size;

    // GEMM1: H = relu(F @ Wg1 + bg1)     [32768 x 256], K=1024
    {
        dim3 grid(HID / BN, BATCH / BM);   // (2, 256)
        gemm_k<0><<<grid, NT>>>(F, wg1, bg1);
    }
    // GEMM2: comp = epi(H @ Wg2 + bg2)   [32768 x 1024], K=256
    {
        dim3 grid(DIM / BN, BATCH / BM);   // (8, 256)
        gemm_k<1><<<grid, NT>>>(F, wg2, bg2);
    }
    // Row-wise post-processing -> out
    {
        dim3 grid(BATCH / R3);             // 1024
        rowpost_k<<<grid, 256>>>(wr1, br1, wr2, br2, wm1, bm1, wm2, bm2, out);
    }
}

// round 6
// speedup vs baseline: 1.0072x; 1.0072x over previous
#include <cuda_runtime.h>
#include <cstdint>
#include <math.h>

#define BATCH 32768
#define DIM   1024
#define HID   256

typedef unsigned long long ull;

// ---------------- device scratch (no runtime allocation) -------------------
__device__ float g_H[(size_t)BATCH * HID];      // 32 MB
__device__ float g_comp[(size_t)BATCH * DIM];   // 128 MB

__device__ __forceinline__ float sigmoidf_(float x) {
    return 1.0f / (1.0f + expf(-x));
}

// packed fp32x2 FMA (sm_103a FFMA2): each half is an independent IEEE-rn fma,
// so per-output accumulation chains are bitwise identical to scalar fmaf.
__device__ __forceinline__ void ffma2(ull& d, ull a, ull b) {
    asm("fma.rn.f32x2 %0, %1, %2, %0;" : "+l"(d) : "l"(a), "l"(b));
}
__device__ __forceinline__ ull pack2(float lo, float hi) {
    ull r;
    asm("mov.b64 %0, {%1, %2};" : "=l"(r) : "f"(lo), "f"(hi));
    return r;
}
__device__ __forceinline__ void unpack2(ull v, float& lo, float& hi) {
    asm("mov.b64 {%0, %1}, %2;" : "=f"(lo), "=f"(hi) : "l"(v));
}

// ---------------------------------------------------------------------------
// fp32 GEMM via packed f32x2 FMA. C[M,N] = epi(A[M,K] @ W[K,N] + bias).
// Numerics: per output, k-ascending fp32 fma chain (identical to R1 kernel,
// which matched the reference with ZERO mask flips; tensor-core orderings
// measurably do not).
// EPI==0: g_H = relu(.)                     A=F, K=1024, N=256
// EPI==1: g_comp = thresh(F * sigmoid(.))   A=g_H, K=256, N=1024
//   (reference "competition" branch is dead code: win == False always)
// ---------------------------------------------------------------------------
#define BM 128
#define BN 128
#define BK 16
#define NT 256

template <int EPI, int K, int N>
__global__ __launch_bounds__(NT, 2) void gemm_f2(
    const float* __restrict__ A,
    const float* __restrict__ W,
    const float* __restrict__ bias,
    const float* __restrict__ F,
    float* __restrict__ C)
{
    constexpr int KT = K / BK;
    __shared__ float As[2][BK][BM];   // transposed A tile
    __shared__ float Ws[2][BK][BN];

    const int tid = threadIdx.x;
    const int tx  = tid & 15;        // 0..15 col group
    const int ty  = tid >> 4;        // 0..15 row group
    const int bx  = blockIdx.x;
    const int by  = blockIdx.y;

    const float* Ab = A + (size_t)by * BM * K;
    const float* Wb = W + (size_t)bx * BN;

    // acc pairs along n: acc2[i][j] = (C[i][2j], C[i][2j+1])
    ull acc2[8][4];
#pragma unroll
    for (int i = 0; i < 8; i++)
#pragma unroll
        for (int j = 0; j < 4; j++) acc2[i][j] = pack2(0.0f, 0.0f);

    // register staging for global->smem
    float4 Ar[2], Wr[2];

    auto ldg_tile = [&](int kt) {
#pragma unroll
        for (int u = 0; u < 2; u++) {
            int l  = tid + u * NT;
            int r  = l >> 2;
            int c4 = l & 3;
            Ar[u] = *(const float4*)(Ab + (size_t)r * K + kt * BK + c4 * 4);
        }
#pragma unroll
        for (int u = 0; u < 2; u++) {
            int l  = tid + u * NT;
            int r  = l >> 5;
            int c4 = l & 31;
            Wr[u] = *(const float4*)(Wb + (size_t)(kt * BK + r) * N + c4 * 4);
        }
    };
    auto sts_tile = [&](int st) {
#pragma unroll
        for (int u = 0; u < 2; u++) {
            int l  = tid + u * NT;
            int r  = l >> 2;
            int c4 = l & 3;
            As[st][c4 * 4 + 0][r] = Ar[u].x;
            As[st][c4 * 4 + 1][r] = Ar[u].y;
            As[st][c4 * 4 + 2][r] = Ar[u].z;
            As[st][c4 * 4 + 3][r] = Ar[u].w;
        }
#pragma unroll
        for (int u = 0; u < 2; u++) {
            int l  = tid + u * NT;
            int r  = l >> 5;
            int c4 = l & 31;
            *(float4*)(&Ws[st][r][c4 * 4]) = Wr[u];
        }
    };

    ldg_tile(0);
    sts_tile(0);
    __syncthreads();

    for (int kt = 0; kt < KT; kt++) {
        const int st = kt & 1;
        if (kt + 1 < KT) ldg_tile(kt + 1);   // hide LDG under compute

#pragma unroll
        for (int k = 0; k < BK; k++) {
            float4 a0 = *(const float4*)&As[st][k][ty * 8];
            float4 a1 = *(const float4*)&As[st][k][ty * 8 + 4];
            float4 b0 = *(const float4*)&Ws[st][k][tx * 8];
            float4 b1 = *(const float4*)&Ws[st][k][tx * 8 + 4];
            ull bb[4] = { pack2(b0.x, b0.y), pack2(b0.z, b0.w),
                          pack2(b1.x, b1.y), pack2(b1.z, b1.w) };
            float av[8] = { a0.x, a0.y, a0.z, a0.w, a1.x, a1.y, a1.z, a1.w };
#pragma unroll
            for (int i = 0; i < 8; i++) {
                ull ad = pack2(av[i], av[i]);
#pragma unroll
                for (int j = 0; j < 4; j++) ffma2(acc2[i][j], ad, bb[j]);
            }
        }

        if (kt + 1 < KT) {
            sts_tile(st ^ 1);
            __syncthreads();
        }
    }

    // epilogue
#pragma unroll
    for (int i = 0; i < 8; i++) {
        size_t r = (size_t)by * BM + ty * 8 + i;
        float xv[8];
#pragma unroll
        for (int j = 0; j < 4; j++) unpack2(acc2[i][j], xv[2 * j], xv[2 * j + 1]);
#pragma unroll
        for (int j = 0; j < 8; j++) {
            int c = bx * BN + tx * 8 + j;
            float x = xv[j] + __ldg(bias + c);
            float o;
            if (EPI == 0) {
                o = fmaxf(x, 0.0f);
            } else {
                float gw = sigmoidf_(x);
                float g  = F[r * DIM + c] * gw;
                o = (g > 0.3f) ? 0.0f : g;    // win == False always
            }
            C[r * N + c] = o;
        }
    }
}

// ---------------------------------------------------------------------------
// Row-wise post-processing. R3=8 rows per 256-thread CTA (4096 CTAs: enough
// parallelism to hide latency; w_r2 re-reads are L2-resident, ~256MB).
// ---------------------------------------------------------------------------
#define R3 8

__global__ __launch_bounds__(256) void rowpost_k(
    const float* __restrict__ w_r1, const float* __restrict__ b_r1,
    const float* __restrict__ w_r2, const float* __restrict__ b_r2,
    const float* __restrict__ w_m1, const float* __restrict__ b_m1,
    const float* __restrict__ w_m2, const float* __restrict__ b_m2,
    float* __restrict__ out)
{
    const int tid  = threadIdx.x;
    const int lane = tid & 31;
    const int wid  = tid >> 5;

    __shared__ float sA[8], sB[8], sC[8], sD[8];

    // per-thread slice of w_r2 / b_r2 (columns tid + 256*j), reused all rows
    float wr2[16][4];
#pragma unroll
    for (int k = 0; k < 16; k++)
#pragma unroll
        for (int j = 0; j < 4; j++)
            wr2[k][j] = __ldg(w_r2 + k * DIM + tid + 256 * j);
    float br2r[4];
#pragma unroll
    for (int j = 0; j < 4; j++) br2r[j] = __ldg(b_r2 + tid + 256 * j);

    for (int rr = 0; rr < R3; rr++) {
        size_t row = (size_t)blockIdx.x * R3 + rr;
        const float* cr = g_comp + row * DIM;

        __syncthreads();   // protect smem reuse across rows

        float v[4];
#pragma unroll
        for (int j = 0; j < 4; j++) v[j] = cr[tid + 256 * j];

        // cur_sp = mean(|comp| < 0.1)
        float cnt = 0.0f;
#pragma unroll
        for (int j = 0; j < 4; j++) cnt += (fabsf(v[j]) < 0.1f) ? 1.0f : 0.0f;
#pragma unroll
        for (int o = 16; o; o >>= 1) cnt += __shfl_xor_sync(0xffffffffu, cnt, o);
        if (lane == 0) sD[wid] = cnt;
        __syncthreads();
        cnt = 0.0f;
#pragma unroll
        for (int w = 0; w < 8; w++) cnt += sD[w];
        float cur_sp = cnt * (1.0f / 1024.0f);

        // hr = relu([cur_sp, 0.1] @ w_r1 + b_r1)
        float hr[16];
#pragma unroll
        for (int k = 0; k < 16; k++) {
            float x = fmaf(cur_sp, __ldg(w_r1 + k),
                      fmaf(0.1f, __ldg(w_r1 + 16 + k), __ldg(b_r1 + k)));
            hr[k] = fmaxf(x, 0.0f);
        }

        // rw = sigmoid(hr @ w_r2 + b_r2); dyn = comp * rw; row stats
        float dyn[4];
        float s1 = 0.0f, s2 = 0.0f, mx = -INFINITY;
#pragma unroll
        for (int j = 0; j < 4; j++) {
            float a = br2r[j];
#pragma unroll
            for (int k = 0; k < 16; k++) a = fmaf(hr[k], wr2[k][j], a);
            float rw = sigmoidf_(a);
            float d  = v[j] * rw;
            dyn[j] = d;
            s1 += d;
            s2 = fmaf(d, d, s2);
            mx = fmaxf(mx, d);
        }
#pragma unroll
        for (int o = 16; o; o >>= 1) {
            s1 += __shfl_xor_sync(0xffffffffu, s1, o);
            s2 += __shfl_xor_sync(0xffffffffu, s2, o);
            mx = fmaxf(mx, __shfl_xor_sync(0xffffffffu, mx, o));
        }
        if (lane == 0) { sA[wid] = s1; sB[wid] = s2; sC[wid] = mx; }
        __syncthreads();
        s1 = 0.0f; s2 = 0.0f; mx = -INFINITY;
#pragma unroll
        for (int w = 0; w < 8; w++) {
            s1 += sA[w]; s2 += sB[w]; mx = fmaxf(mx, sC[w]);
        }

        float fmean = s1 * (1.0f / 1024.0f);
        float var   = (s2 - s1 * fmean) * (1.0f / 1023.0f);   // ddof=1
        var = fmaxf(var, 0.0f);
        float fstd = sqrtf(var);

        // thr = sigmoid(relu([fmean, fstd, fmax] @ w_m1 + b_m1) @ w_m2 + b_m2)
        float a2 = __ldg(b_m2);
#pragma unroll
        for (int k = 0; k < 16; k++) {
            float x = fmaf(fmean, __ldg(w_m1 + k),
                      fmaf(fstd, __ldg(w_m1 + 16 + k),
                      fmaf(mx,   __ldg(w_m1 + 32 + k), __ldg(b_m1 + k))));
            a2 = fmaf(fmaxf(x, 0.0f), __ldg(w_m2 + k), a2);
        }
        float thr = sigmoidf_(a2);

        float* orow = out + row * DIM;
#pragma unroll
        for (int j = 0; j < 4; j++)
            orow[tid + 256 * j] = (fabsf(dyn[j]) > thr) ? dyn[j] : 0.0f;
    }
}

// ---------------------------------------------------------------------------
// Launch
// ---------------------------------------------------------------------------
extern "C" void kernel_launch(void* const* d_in, const int* in_sizes, int n_in,
                              void* d_out, int out_size)
{
    const float* F   = (const float*)d_in[0];
    const float* wg1 = (const float*)d_in[1];
    const float* bg1 = (const float*)d_in[2];
    const float* wg2 = (const float*)d_in[3];
    const float* bg2 = (const float*)d_in[4];
    // d_in[5..8] = competition weights: dead code (win == False always)
    const float* wr1 = (const float*)d_in[9];
    const float* br1 = (const float*)d_in[10];
    const float* wr2 = (const float*)d_in[11];
    const float* br2 = (const float*)d_in[12];
    const float* wm1 = (const float*)d_in[13];
    const float* bm1 = (const float*)d_in[14];
    const float* wm2 = (const float*)d_in[15];
    const float* bm2 = (const float*)d_in[16];
    float* out = (float*)d_out;
    (void)in_sizes; (void)n_in; (void)out_size;

    float *H, *comp;
    cudaGetSymbolAddress((void**)&H, g_H);
    cudaGetSymbolAddress((void**)&comp, g_comp);

    // GEMM1: H = relu(F @ Wg1 + bg1)      [32768 x 256], K=1024
    gemm_f2<0, DIM, HID><<<dim3(HID / BN, BATCH / BM), NT>>>(F, wg1, bg1, nullptr, H);
    // GEMM2: comp = thresh(F*sigmoid(H @ Wg2 + bg2))  [32768 x 1024], K=256
    gemm_f2<1, HID, DIM><<<dim3(DIM / BN, BATCH / BM), NT>>>(H, wg2, bg2, F, comp);
    // row-wise post-processing
    rowpost_k<<<BATCH / R3, 256>>>(wr1, br1, wr2, br2, wm1, bm1, wm2, bm2, out);
}

// round 7
// speedup vs baseline: 1.0137x; 1.0064x over previous
#include <cuda_runtime.h>
#include <cstdint>
#include <math.h>

#define BATCH 32768
#define DIM   1024
#define HID   256

typedef unsigned long long ull;

// ---------------- device scratch (no runtime allocation) -------------------
__device__ float g_H[(size_t)BATCH * HID];      // 32 MB
__device__ float g_comp[(size_t)BATCH * DIM];   // 128 MB

__device__ __forceinline__ float sigmoidf_(float x) {
    return 1.0f / (1.0f + expf(-x));
}

// packed fp32x2 FMA (sm_103a FFMA2): each half is an independent IEEE-rn fma,
// so per-output accumulation chains are bitwise identical to scalar fmaf.
__device__ __forceinline__ void ffma2(ull& d, ull a, ull b) {
    asm("fma.rn.f32x2 %0, %1, %2, %0;" : "+l"(d) : "l"(a), "l"(b));
}
__device__ __forceinline__ ull pack2(float lo, float hi) {
    ull r;
    asm("mov.b64 %0, {%1, %2};" : "=l"(r) : "f"(lo), "f"(hi));
    return r;
}
__device__ __forceinline__ void unpack2(ull v, float& lo, float& hi) {
    asm("mov.b64 {%0, %1}, %2;" : "=f"(lo), "=f"(hi) : "l"(v));
}

// ---------------------------------------------------------------------------
// fp32 GEMM, hierarchical tiling:
//   CTA 128x128, BK=16, 8 warps as 4(m) x 2(n)  -> warp tile 32x64
//   lanes as 4(m) x 8(n), thread tile 8x8
// Per warp per k-step the smem requests hit only 4 A-lines + 8 B-lines
// (broadcast within lane groups) -> smem is no longer the binding pipe
// (R6's tx/ty grid made every warp re-read all of BN -> L1 74%, fma 47%).
// Numerics: per-output k-ascending fp32 fma chains, identical to R1/R6.
// EPI==0: g_H = relu(.)                     A=F, K=1024, N=256
// EPI==1: g_comp = thresh(F * sigmoid(.))   A=g_H, K=256, N=1024
//   (reference "competition" branch is dead code: win == False always)
// ---------------------------------------------------------------------------
#define BM 128
#define BN 128
#define BK 16
#define NT 256

template <int EPI, int K, int N>
__global__ __launch_bounds__(NT, 2) void gemm_f2(
    const float* __restrict__ A,
    const float* __restrict__ W,
    const float* __restrict__ bias,
    const float* __restrict__ F,
    float* __restrict__ C)
{
    constexpr int KT = K / BK;
    __shared__ float As[2][BK][BM];   // transposed A tile
    __shared__ float Ws[2][BK][BN];

    const int tid   = threadIdx.x;
    const int lane  = tid & 31;
    const int wid   = tid >> 5;
    const int warpM = wid & 3;        // 0..3 -> m offset *32
    const int warpN = wid >> 2;       // 0..1 -> n offset *64
    const int lm    = lane >> 3;      // 0..3 -> m sub *8
    const int ln    = lane & 7;       // 0..7 -> n sub *8
    const int row0  = warpM * 32 + lm * 8;
    const int col0  = warpN * 64 + ln * 8;

    const int bx = blockIdx.x;
    const int by = blockIdx.y;

    const float* Ab = A + (size_t)by * BM * K;
    const float* Wb = W + (size_t)bx * BN;

    // acc pairs along n: acc2[i][j] = (C[row0+i][col0+2j], C[row0+i][col0+2j+1])
    ull acc2[8][4];
#pragma unroll
    for (int i = 0; i < 8; i++)
#pragma unroll
        for (int j = 0; j < 4; j++) acc2[i][j] = pack2(0.0f, 0.0f);

    // register staging for global->smem
    float4 Ar[2], Wr[2];

    auto ldg_tile = [&](int kt) {
#pragma unroll
        for (int u = 0; u < 2; u++) {
            int l  = tid + u * NT;
            int r  = l >> 2;
            int c4 = l & 3;
            Ar[u] = *(const float4*)(Ab + (size_t)r * K + kt * BK + c4 * 4);
        }
#pragma unroll
        for (int u = 0; u < 2; u++) {
            int l  = tid + u * NT;
            int r  = l >> 5;
            int c4 = l & 31;
            Wr[u] = *(const float4*)(Wb + (size_t)(kt * BK + r) * N + c4 * 4);
        }
    };
    auto sts_tile = [&](int st) {
#pragma unroll
        for (int u = 0; u < 2; u++) {
            int l  = tid + u * NT;
            int r  = l >> 2;
            int c4 = l & 3;
            As[st][c4 * 4 + 0][r] = Ar[u].x;
            As[st][c4 * 4 + 1][r] = Ar[u].y;
            As[st][c4 * 4 + 2][r] = Ar[u].z;
            As[st][c4 * 4 + 3][r] = Ar[u].w;
        }
#pragma unroll
        for (int u = 0; u < 2; u++) {
            int l  = tid + u * NT;
            int r  = l >> 5;
            int c4 = l & 31;
            *(float4*)(&Ws[st][r][c4 * 4]) = Wr[u];
        }
    };

    ldg_tile(0);
    sts_tile(0);
    __syncthreads();

    for (int kt = 0; kt < KT; kt++) {
        const int st = kt & 1;
        if (kt + 1 < KT) ldg_tile(kt + 1);   // hide LDG under compute

#pragma unroll
        for (int k = 0; k < BK; k++) {
            float4 a0 = *(const float4*)&As[st][k][row0];
            float4 a1 = *(const float4*)&As[st][k][row0 + 4];
            float4 b0 = *(const float4*)&Ws[st][k][col0];
            float4 b1 = *(const float4*)&Ws[st][k][col0 + 4];
            ull bb[4] = { pack2(b0.x, b0.y), pack2(b0.z, b0.w),
                          pack2(b1.x, b1.y), pack2(b1.z, b1.w) };
            float av[8] = { a0.x, a0.y, a0.z, a0.w, a1.x, a1.y, a1.z, a1.w };
#pragma unroll
            for (int i = 0; i < 8; i++) {
                ull ad = pack2(av[i], av[i]);
#pragma unroll
                for (int j = 0; j < 4; j++) ffma2(acc2[i][j], ad, bb[j]);
            }
        }

        if (kt + 1 < KT) {
            sts_tile(st ^ 1);
            __syncthreads();
        }
    }

    // epilogue
#pragma unroll
    for (int i = 0; i < 8; i++) {
        size_t r = (size_t)by * BM + row0 + i;
        float xv[8];
#pragma unroll
        for (int j = 0; j < 4; j++) unpack2(acc2[i][j], xv[2 * j], xv[2 * j + 1]);
#pragma unroll
        for (int j = 0; j < 8; j++) {
            int c = bx * BN + col0 + j;
            float x = xv[j] + __ldg(bias + c);
            float o;
            if (EPI == 0) {
                o = fmaxf(x, 0.0f);
            } else {
                float gw = sigmoidf_(x);
                float g  = F[r * DIM + c] * gw;
                o = (g > 0.3f) ? 0.0f : g;    // win == False always
            }
            C[r * N + c] = o;
        }
    }
}

// ---------------------------------------------------------------------------
// Row-wise post-processing. R3=8 rows per 256-thread CTA (4096 CTAs).
// ---------------------------------------------------------------------------
#define R3 8

__global__ __launch_bounds__(256) void rowpost_k(
    const float* __restrict__ w_r1, const float* __restrict__ b_r1,
    const float* __restrict__ w_r2, const float* __restrict__ b_r2,
    const float* __restrict__ w_m1, const float* __restrict__ b_m1,
    const float* __restrict__ w_m2, const float* __restrict__ b_m2,
    float* __restrict__ out)
{
    const int tid  = threadIdx.x;
    const int lane = tid & 31;
    const int wid  = tid >> 5;

    __shared__ float sA[8], sB[8], sC[8], sD[8];

    // per-thread slice of w_r2 / b_r2 (columns tid + 256*j), reused all rows
    float wr2[16][4];
#pragma unroll
    for (int k = 0; k < 16; k++)
#pragma unroll
        for (int j = 0; j < 4; j++)
            wr2[k][j] = __ldg(w_r2 + k * DIM + tid + 256 * j);
    float br2r[4];
#pragma unroll
    for (int j = 0; j < 4; j++) br2r[j] = __ldg(b_r2 + tid + 256 * j);

    for (int rr = 0; rr < R3; rr++) {
        size_t row = (size_t)blockIdx.x * R3 + rr;
        const float* cr = g_comp + row * DIM;

        __syncthreads();   // protect smem reuse across rows

        float v[4];
#pragma unroll
        for (int j = 0; j < 4; j++) v[j] = cr[tid + 256 * j];

        // cur_sp = mean(|comp| < 0.1)
        float cnt = 0.0f;
#pragma unroll
        for (int j = 0; j < 4; j++) cnt += (fabsf(v[j]) < 0.1f) ? 1.0f : 0.0f;
#pragma unroll
        for (int o = 16; o; o >>= 1) cnt += __shfl_xor_sync(0xffffffffu, cnt, o);
        if (lane == 0) sD[wid] = cnt;
        __syncthreads();
        cnt = 0.0f;
#pragma unroll
        for (int w = 0; w < 8; w++) cnt += sD[w];
        float cur_sp = cnt * (1.0f / 1024.0f);

        // hr = relu([cur_sp, 0.1] @ w_r1 + b_r1)
        float hr[16];
#pragma unroll
        for (int k = 0; k < 16; k++) {
            float x = fmaf(cur_sp, __ldg(w_r1 + k),
                      fmaf(0.1f, __ldg(w_r1 + 16 + k), __ldg(b_r1 + k)));
            hr[k] = fmaxf(x, 0.0f);
        }

        // rw = sigmoid(hr @ w_r2 + b_r2); dyn = comp * rw; row stats
        float dyn[4];
        float s1 = 0.0f, s2 = 0.0f, mx = -INFINITY;
#pragma unroll
        for (int j = 0; j < 4; j++) {
            float a = br2r[j];
#pragma unroll
            for (int k = 0; k < 16; k++) a = fmaf(hr[k], wr2[k][j], a);
            float rw = sigmoidf_(a);
            float d  = v[j] * rw;
            dyn[j] = d;
            s1 += d;
            s2 = fmaf(d, d, s2);
            mx = fmaxf(mx, d);
        }
#pragma unroll
        for (int o = 16; o; o >>= 1) {
            s1 += __shfl_xor_sync(0xffffffffu, s1, o);
            s2 += __shfl_xor_sync(0xffffffffu, s2, o);
            mx = fmaxf(mx, __shfl_xor_sync(0xffffffffu, mx, o));
        }
        if (lane == 0) { sA[wid] = s1; sB[wid] = s2; sC[wid] = mx; }
        __syncthreads();
        s1 = 0.0f; s2 = 0.0f; mx = -INFINITY;
#pragma unroll
        for (int w = 0; w < 8; w++) {
            s1 += sA[w]; s2 += sB[w]; mx = fmaxf(mx, sC[w]);
        }

        float fmean = s1 * (1.0f / 1024.0f);
        float var   = (s2 - s1 * fmean) * (1.0f / 1023.0f);   // ddof=1
        var = fmaxf(var, 0.0f);
        float fstd = sqrtf(var);

        // thr = sigmoid(relu([fmean, fstd, fmax] @ w_m1 + b_m1) @ w_m2 + b_m2)
        float a2 = __ldg(b_m2);
#pragma unroll
        for (int k = 0; k < 16; k++) {
            float x = fmaf(fmean, __ldg(w_m1 + k),
                      fmaf(fstd, __ldg(w_m1 + 16 + k),
                      fmaf(mx,   __ldg(w_m1 + 32 + k), __ldg(b_m1 + k))));
            a2 = fmaf(fmaxf(x, 0.0f), __ldg(w_m2 + k), a2);
        }
        float thr = sigmoidf_(a2);

        float* orow = out + row * DIM;
#pragma unroll
        for (int j = 0; j < 4; j++)
            orow[tid + 256 * j] = (fabsf(dyn[j]) > thr) ? dyn[j] : 0.0f;
    }
}

// ---------------------------------------------------------------------------
// Launch
// ---------------------------------------------------------------------------
extern "C" void kernel_launch(void* const* d_in, const int* in_sizes, int n_in,
                              void* d_out, int out_size)
{
    const float* F   = (const float*)d_in[0];
    const float* wg1 = (const float*)d_in[1];
    const float* bg1 = (const float*)d_in[2];
    const float* wg2 = (const float*)d_in[3];
    const float* bg2 = (const float*)d_in[4];
    // d_in[5..8] = competition weights: dead code (win == False always)
    const float* wr1 = (const float*)d_in[9];
    const float* br1 = (const float*)d_in[10];
    const float* wr2 = (const float*)d_in[11];
    const float* br2 = (const float*)d_in[12];
    const float* wm1 = (const float*)d_in[13];
    const float* bm1 = (const float*)d_in[14];
    const float* wm2 = (const float*)d_in[15];
    const float* bm2 = (const float*)d_in[16];
    float* out = (float*)d_out;
    (void)in_sizes; (void)n_in; (void)out_size;

    float *H, *comp;
    cudaGetSymbolAddress((void**)&H, g_H);
    cudaGetSymbolAddress((void**)&comp, g_comp);

    // GEMM1: H = relu(F @ Wg1 + bg1)      [32768 x 256], K=1024
    gemm_f2<0, DIM, HID><<<dim3(HID / BN, BATCH / BM), NT>>>(F, wg1, bg1, nullptr, H);
    // GEMM2: comp = thresh(F*sigmoid(H @ Wg2 + bg2))  [32768 x 1024], K=256
    gemm_f2<1, HID, DIM><<<dim3(DIM / BN, BATCH / BM), NT>>>(H, wg2, bg2, F, comp);
    // row-wise post-processing
    rowpost_k<<<BATCH / R3, 256>>>(wr1, br1, wr2, br2, wm1, bm1, wm2, bm2, out);
}

// round 8
// speedup vs baseline: 1.2948x; 1.2773x over previous
#include <cuda_runtime.h>
#include <cstdint>
#include <math.h>

#define BATCH 32768
#define DIM   1024
#define HID   256

typedef unsigned long long ull;

// ---------------- device scratch (no runtime allocation) -------------------
__device__ float g_H[(size_t)BATCH * HID];      // 32 MB
__device__ float g_comp[(size_t)BATCH * DIM];   // 128 MB

__device__ __forceinline__ float sigmoidf_(float x) {
    return 1.0f / (1.0f + expf(-x));
}

// packed fp32x2 FMA: each half is an independent IEEE-rn fp32 fma -> per-output
// accumulation chains bitwise identical to scalar fmaf (k ascending).
__device__ __forceinline__ void ffma2(ull& d, ull a, ull b) {
    asm("fma.rn.f32x2 %0, %1, %2, %0;" : "+l"(d) : "l"(a), "l"(b));
}
__device__ __forceinline__ ull pack2(float lo, float hi) {
    ull r;
    asm("mov.b64 %0, {%1, %2};" : "=l"(r) : "f"(lo), "f"(hi));
    return r;
}
__device__ __forceinline__ void unpack2(ull v, float& lo, float& hi) {
    asm("mov.b64 {%0, %1}, %2;" : "=f"(lo), "=f"(hi) : "l"(v));
}

__device__ __forceinline__ void cp16(void* s, const void* g) {
    uint32_t sa = (uint32_t)__cvta_generic_to_shared(s);
    asm volatile("cp.async.cg.shared.global [%0], [%1], 16;\n" :: "r"(sa), "l"(g));
}
#define CP_COMMIT() asm volatile("cp.async.commit_group;\n")
#define CP_WAIT0()  asm volatile("cp.async.wait_group 0;\n")

// ---------------------------------------------------------------------------
// fp32 GEMM, latency-optimized:
//  - CTA 128x128, BK=16; warps 2(M)x4(N) -> warp tile 64x32
//  - lanes 8(M)x4(N); thread tile rows {rA..+3, rA+32..+3} x cols {cB..+3, cB+16..+3}
//    -> all 4 frag LDS.128 are 1-wavefront (consecutive 16B chunks / broadcast)
//  - register fragment double-buffer (load k+1 during k's FMAs)
//  - B tile via cp.async; A via LDG + transposed STS; ONE syncthreads per tile
// Numerics: per-output k-ascending fp32 fma chains == R1/R6/R7 bitwise.
// EPI==0: g_H = relu(.)                    A=F, K=1024, N=256
// EPI==1: g_comp = thresh(F * sigmoid(.))  A=g_H, K=256, N=1024
//   (reference "competition" branch is dead code: win == False always)
// ---------------------------------------------------------------------------
#define BM 128
#define BN 128
#define BK 16
#define BM2 132    // padded As row (floats): 528B, 16B-aligned, low-conflict
#define NT 256

struct Frag { float4 a0, a1, b0, b1; };

template <int EPI, int K, int N>
__global__ __launch_bounds__(NT, 2) void gemm_f2(
    const float* __restrict__ A,
    const float* __restrict__ W,
    const float* __restrict__ bias,
    const float* __restrict__ F,
    float* __restrict__ C)
{
    constexpr int KT = K / BK;
    __shared__ float As[2][BK][BM2];
    __shared__ __align__(16) float Ws[2][BK][BN];

    const int tid   = threadIdx.x;
    const int lane  = tid & 31;
    const int wid   = tid >> 5;
    const int warpM = wid & 1;         // 0..1 -> m *64
    const int warpN = wid >> 1;        // 0..3 -> n *32
    const int lm8   = lane >> 2;       // 0..7
    const int ln4   = lane & 3;        // 0..3
    const int rA    = warpM * 64 + lm8 * 4;   // rows rA..rA+3 and rA+32..rA+35
    const int cB    = warpN * 32 + ln4 * 4;   // cols cB..cB+3 and cB+16..cB+19

    const int bx = blockIdx.x, by = blockIdx.y;
    const float* Ab = A + (size_t)by * BM * K;
    const float* Wb = W + (size_t)bx * BN;

    ull acc2[8][4];
#pragma unroll
    for (int i = 0; i < 8; i++)
#pragma unroll
        for (int j = 0; j < 4; j++) acc2[i][j] = pack2(0.0f, 0.0f);

    float4 Ar[2];

    auto ldgA = [&](int kt) {
#pragma unroll
        for (int u = 0; u < 2; u++) {
            int l = tid + u * NT, r = l >> 2, c4 = l & 3;
            Ar[u] = *(const float4*)(Ab + (size_t)r * K + kt * BK + c4 * 4);
        }
    };
    auto stsA = [&](int st) {
#pragma unroll
        for (int u = 0; u < 2; u++) {
            int l = tid + u * NT, r = l >> 2, c4 = l & 3;
            As[st][c4 * 4 + 0][r] = Ar[u].x;
            As[st][c4 * 4 + 1][r] = Ar[u].y;
            As[st][c4 * 4 + 2][r] = Ar[u].z;
            As[st][c4 * 4 + 3][r] = Ar[u].w;
        }
    };
    auto cpB = [&](int kt, int st) {
#pragma unroll
        for (int u = 0; u < 2; u++) {
            int l = tid + u * NT, kk = l >> 5, c16 = l & 31;
            cp16(&Ws[st][kk][c16 * 4],
                 Wb + (size_t)(kt * BK + kk) * N + c16 * 4);
        }
    };
    auto lds_frag = [&](Frag& f, int st, int k) {
        f.a0 = *(const float4*)&As[st][k][rA];
        f.a1 = *(const float4*)&As[st][k][rA + 32];
        f.b0 = *(const float4*)&Ws[st][k][cB];
        f.b1 = *(const float4*)&Ws[st][k][cB + 16];
    };
    auto fma_step = [&](const Frag& f) {
        ull bb[4] = { pack2(f.b0.x, f.b0.y), pack2(f.b0.z, f.b0.w),
                      pack2(f.b1.x, f.b1.y), pack2(f.b1.z, f.b1.w) };
        float av[8] = { f.a0.x, f.a0.y, f.a0.z, f.a0.w,
                        f.a1.x, f.a1.y, f.a1.z, f.a1.w };
#pragma unroll
        for (int i = 0; i < 8; i++) {
            ull ad = pack2(av[i], av[i]);
#pragma unroll
            for (int j = 0; j < 4; j++) ffma2(acc2[i][j], ad, bb[j]);
        }
    };

    // prologue: tile 0 into stage 0
    ldgA(0);
    cpB(0, 0);
    CP_COMMIT();
    stsA(0);
    CP_WAIT0();
    __syncthreads();

    Frag fr[2];
    lds_frag(fr[0], 0, 0);

    for (int kt = 0; kt < KT; kt++) {
        const int st = kt & 1;
        if (kt + 1 < KT) { ldgA(kt + 1); cpB(kt + 1, st ^ 1); CP_COMMIT(); }
#pragma unroll
        for (int k = 0; k < BK; k++) {
            const int nb = (k + 1) & 1;
            if (k < BK - 1) {
                lds_frag(fr[nb], st, k + 1);
            } else if (kt + 1 < KT) {
                stsA(st ^ 1);          // A tile for kt+1
                CP_WAIT0();            // B tile for kt+1 arrived
                __syncthreads();       // one barrier per tile
                lds_frag(fr[nb], st ^ 1, 0);
            }
            fma_step(fr[k & 1]);
        }
    }

    // epilogue: rows rA + (i>>2)*32 + (i&3), col groups cB and cB+16
#pragma unroll
    for (int i = 0; i < 8; i++) {
        size_t r = (size_t)by * BM + rA + (i >> 2) * 32 + (i & 3);
        float xv[8];
#pragma unroll
        for (int j = 0; j < 4; j++) unpack2(acc2[i][j], xv[2 * j], xv[2 * j + 1]);
#pragma unroll
        for (int gidx = 0; gidx < 2; gidx++) {
            int cbase = bx * BN + cB + gidx * 16;
            float4 res;
            float x0 = xv[gidx * 4 + 0] + __ldg(bias + cbase + 0);
            float x1 = xv[gidx * 4 + 1] + __ldg(bias + cbase + 1);
            float x2 = xv[gidx * 4 + 2] + __ldg(bias + cbase + 2);
            float x3 = xv[gidx * 4 + 3] + __ldg(bias + cbase + 3);
            if (EPI == 0) {
                res.x = fmaxf(x0, 0.f); res.y = fmaxf(x1, 0.f);
                res.z = fmaxf(x2, 0.f); res.w = fmaxf(x3, 0.f);
            } else {
                float4 f4 = *(const float4*)(F + r * N + cbase);
                float g0 = f4.x * sigmoidf_(x0), g1 = f4.y * sigmoidf_(x1);
                float g2 = f4.z * sigmoidf_(x2), g3 = f4.w * sigmoidf_(x3);
                res.x = (g0 > 0.3f) ? 0.f : g0;  res.y = (g1 > 0.3f) ? 0.f : g1;
                res.z = (g2 > 0.3f) ? 0.f : g2;  res.w = (g3 > 0.3f) ? 0.f : g3;
            }
            *(float4*)(C + r * N + cbase) = res;
        }
    }
}

// ---------------------------------------------------------------------------
// Row-wise post-processing (unchanged from R7).
// ---------------------------------------------------------------------------
#define R3 8

__global__ __launch_bounds__(256) void rowpost_k(
    const float* __restrict__ w_r1, const float* __restrict__ b_r1,
    const float* __restrict__ w_r2, const float* __restrict__ b_r2,
    const float* __restrict__ w_m1, const float* __restrict__ b_m1,
    const float* __restrict__ w_m2, const float* __restrict__ b_m2,
    float* __restrict__ out)
{
    const int tid  = threadIdx.x;
    const int lane = tid & 31;
    const int wid  = tid >> 5;

    __shared__ float sA[8], sB[8], sC[8], sD[8];

    float wr2[16][4];
#pragma unroll
    for (int k = 0; k < 16; k++)
#pragma unroll
        for (int j = 0; j < 4; j++)
            wr2[k][j] = __ldg(w_r2 + k * DIM + tid + 256 * j);
    float br2r[4];
#pragma unroll
    for (int j = 0; j < 4; j++) br2r[j] = __ldg(b_r2 + tid + 256 * j);

    for (int rr = 0; rr < R3; rr++) {
        size_t row = (size_t)blockIdx.x * R3 + rr;
        const float* cr = g_comp + row * DIM;

        __syncthreads();

        float v[4];
#pragma unroll
        for (int j = 0; j < 4; j++) v[j] = cr[tid + 256 * j];

        float cnt = 0.0f;
#pragma unroll
        for (int j = 0; j < 4; j++) cnt += (fabsf(v[j]) < 0.1f) ? 1.0f : 0.0f;
#pragma unroll
        for (int o = 16; o; o >>= 1) cnt += __shfl_xor_sync(0xffffffffu, cnt, o);
        if (lane == 0) sD[wid] = cnt;
        __syncthreads();
        cnt = 0.0f;
#pragma unroll
        for (int w = 0; w < 8; w++) cnt += sD[w];
        float cur_sp = cnt * (1.0f / 1024.0f);

        float hr[16];
#pragma unroll
        for (int k = 0; k < 16; k++) {
            float x = fmaf(cur_sp, __ldg(w_r1 + k),
                      fmaf(0.1f, __ldg(w_r1 + 16 + k), __ldg(b_r1 + k)));
            hr[k] = fmaxf(x, 0.0f);
        }

        float dyn[4];
        float s1 = 0.0f, s2 = 0.0f, mx = -INFINITY;
#pragma unroll
        for (int j = 0; j < 4; j++) {
            float a = br2r[j];
#pragma unroll
            for (int k = 0; k < 16; k++) a = fmaf(hr[k], wr2[k][j], a);
            float rw = sigmoidf_(a);
            float d  = v[j] * rw;
            dyn[j] = d;
            s1 += d;
            s2 = fmaf(d, d, s2);
            mx = fmaxf(mx, d);
        }
#pragma unroll
        for (int o = 16; o; o >>= 1) {
            s1 += __shfl_xor_sync(0xffffffffu, s1, o);
            s2 += __shfl_xor_sync(0xffffffffu, s2, o);
            mx = fmaxf(mx, __shfl_xor_sync(0xffffffffu, mx, o));
        }
        if (lane == 0) { sA[wid] = s1; sB[wid] = s2; sC[wid] = mx; }
        __syncthreads();
        s1 = 0.0f; s2 = 0.0f; mx = -INFINITY;
#pragma unroll
        for (int w = 0; w < 8; w++) {
            s1 += sA[w]; s2 += sB[w]; mx = fmaxf(mx, sC[w]);
        }

        float fmean = s1 * (1.0f / 1024.0f);
        float var   = (s2 - s1 * fmean) * (1.0f / 1023.0f);   // ddof=1
        var = fmaxf(var, 0.0f);
        float fstd = sqrtf(var);

        float a2 = __ldg(b_m2);
#pragma unroll
        for (int k = 0; k < 16; k++) {
            float x = fmaf(fmean, __ldg(w_m1 + k),
                      fmaf(fstd, __ldg(w_m1 + 16 + k),
                      fmaf(mx,   __ldg(w_m1 + 32 + k), __ldg(b_m1 + k))));
            a2 = fmaf(fmaxf(x, 0.0f), __ldg(w_m2 + k), a2);
        }
        float thr = sigmoidf_(a2);

        float* orow = out + row * DIM;
#pragma unroll
        for (int j = 0; j < 4; j++)
            orow[tid + 256 * j] = (fabsf(dyn[j]) > thr) ? dyn[j] : 0.0f;
    }
}

// ---------------------------------------------------------------------------
// Launch
// ---------------------------------------------------------------------------
extern "C" void kernel_launch(void* const* d_in, const int* in_sizes, int n_in,
                              void* d_out, int out_size)
{
    const float* F   = (const float*)d_in[0];
    const float* wg1 = (const float*)d_in[1];
    const float* bg1 = (const float*)d_in[2];
    const float* wg2 = (const float*)d_in[3];
    const float* bg2 = (const float*)d_in[4];
    // d_in[5..8] = competition weights: dead code (win == False always)
    const float* wr1 = (const float*)d_in[9];
    const float* br1 = (const float*)d_in[10];
    const float* wr2 = (const float*)d_in[11];
    const float* br2 = (const float*)d_in[12];
    const float* wm1 = (const float*)d_in[13];
    const float* bm1 = (const float*)d_in[14];
    const float* wm2 = (const float*)d_in[15];
    const float* bm2 = (const float*)d_in[16];
    float* out = (float*)d_out;
    (void)in_sizes; (void)n_in; (void)out_size;

    float *H, *comp;
    cudaGetSymbolAddress((void**)&H, g_H);
    cudaGetSymbolAddress((void**)&comp, g_comp);

    // GEMM1: H = relu(F @ Wg1 + bg1)      [32768 x 256], K=1024
    gemm_f2<0, DIM, HID><<<dim3(HID / BN, BATCH / BM), NT>>>(F, wg1, bg1, nullptr, H);
    // GEMM2: comp = thresh(F*sigmoid(H @ Wg2 + bg2))  [32768 x 1024], K=256
    gemm_f2<1, HID, DIM><<<dim3(DIM / BN, BATCH / BM), NT>>>(H, wg2, bg2, F, comp);
    // row-wise post-processing
    rowpost_k<<<BATCH / R3, 256>>>(wr1, br1, wr2, br2, wm1, bm1, wm2, bm2, out);
}